// round 13
// baseline (speedup 1.0000x reference)
#include <cuda_runtime.h>
#include <cuda_fp16.h>
#include <math.h>

#define NNODES 100000
#define NPAD   100096
#define FIN    128
#define HID    256
#define NCLS   40
#define EMAX   1600000
#define NBLK256 ((NNODES + 255) / 256)   // 391
#define NXCONV  (NNODES * (FIN / 4))     // 3.2M float4 elements

// ---------------- scratch ----------------
__device__ __half g_bufA[(size_t)NPAD * HID];
__device__ __half g_bufB[(size_t)NPAD * HID];
__device__ __half g_W1T[256 * 128];
__device__ __half g_W2T[256 * 256];
__device__ __half g_W3T[256 * 256];
__device__ __half g_W4T[40 * 256];
__device__ float g_dinv[NNODES];
__device__ int   g_hist[NNODES];
__device__ int   g_rowptr[NNODES + 1];
__device__ int   g_fill[NNODES];
__device__ int   g_col[EMAX];
__device__ int   g_bsum[NBLK256];
__device__ int   g_boff[NBLK256];

__device__ __forceinline__ __half* selbuf(int s) { return s ? g_bufB : g_bufA; }

__device__ __forceinline__ void h8_to_f8(uint4 v, float* f) {
    const __half2* h = reinterpret_cast<const __half2*>(&v);
#pragma unroll
    for (int k = 0; k < 4; k++) {
        float2 t = __half22float2(h[k]);
        f[2 * k] = t.x;
        f[2 * k + 1] = t.y;
    }
}
__device__ __forceinline__ uint4 f8_to_h8(const float* f) {
    uint4 o;
    __half2* h = reinterpret_cast<__half2*>(&o);
#pragma unroll
    for (int k = 0; k < 4; k++) h[k] = __floats2half2_rn(f[2 * k], f[2 * k + 1]);
    return o;
}

// ---------------- fused prep: xconv + hist-init + weight conversion ----------------
__global__ void k_prep(const float* __restrict__ x,
                       const float* __restrict__ W1, const float* __restrict__ W2,
                       const float* __restrict__ W3, const float* __restrict__ W4,
                       int xdst_sel) {
    const int i = blockIdx.x * blockDim.x + threadIdx.x;
    if (i < NXCONV) {
        float4 v = reinterpret_cast<const float4*>(x)[i];
        uint2 o;
        __half2* oh = reinterpret_cast<__half2*>(&o);
        oh[0] = __floats2half2_rn(v.x, v.y);
        oh[1] = __floats2half2_rn(v.z, v.w);
        reinterpret_cast<uint2*>(selbuf(xdst_sel))[i] = o;
    }
    if (i < NNODES) g_hist[i] = 0;
    if (i < 256 * 256) {
        int n = i >> 8, k = i & 255;
        int ko = (k & ~15) + 2 * ((k >> 2) & 3) + (k & 1) + (((k >> 1) & 1) << 3);
        g_W2T[n * 256 + k] = __float2half(W2[ko * 256 + n]);
        g_W3T[n * 256 + k] = __float2half(W3[ko * 256 + n]);
    }
    if (i < 256 * 128) {
        int n = i >> 7, k = i & 127;
        int ko = (k & ~15) + 2 * ((k >> 2) & 3) + (k & 1) + (((k >> 1) & 1) << 3);
        g_W1T[n * 128 + k] = __float2half(W1[ko * 256 + n]);
    }
    if (i < 40 * 256) {
        int n = i >> 8, k = i & 255;
        int ko = (k & ~15) + 2 * ((k >> 2) & 3) + (k & 1) + (((k >> 1) & 1) << 3);
        g_W4T[n * 256 + k] = __float2half(W4[ko * NCLS + n]);
    }
}

// ---------------- CSR build ----------------
__global__ void k_hist(const int* __restrict__ ei, int E) {
    int e = blockIdx.x * blockDim.x + threadIdx.x;
    if (e < E) atomicAdd(&g_hist[ei[E + e]], 1);
}

__global__ void k_scan_s1() {
    __shared__ int s[256];
    const int t = threadIdx.x;
    const int i = blockIdx.x * 256 + t;
    s[t] = (i < NNODES) ? g_hist[i] : 0;
    __syncthreads();
    for (int off = 128; off; off >>= 1) {
        if (t < off) s[t] += s[t + off];
        __syncthreads();
    }
    if (t == 0) g_bsum[blockIdx.x] = s[0];
}

__global__ void k_scan_s2() {
    __shared__ int s[512];
    const int t = threadIdx.x;
    s[t] = (t < NBLK256) ? g_bsum[t] : 0;
    __syncthreads();
    for (int off = 1; off < 512; off <<= 1) {
        int v = (t >= off) ? s[t - off] : 0;
        __syncthreads();
        s[t] += v;
        __syncthreads();
    }
    if (t < NBLK256) g_boff[t] = (t == 0) ? 0 : s[t - 1];
}

__global__ void k_scan_s3(int E) {
    __shared__ int s[256];
    const int t = threadIdx.x;
    const int i = blockIdx.x * 256 + t;
    const int h = (i < NNODES) ? g_hist[i] : 0;
    s[t] = h;
    __syncthreads();
    for (int off = 1; off < 256; off <<= 1) {
        int v = (t >= off) ? s[t - off] : 0;
        __syncthreads();
        s[t] += v;
        __syncthreads();
    }
    if (i < NNODES) {
        const int ex = g_boff[blockIdx.x] + s[t] - h;
        g_rowptr[i] = ex;
        g_fill[i] = ex;
        g_dinv[i] = rsqrtf((float)(h + 1));
    }
    if (i == 0) g_rowptr[NNODES] = E;
}

__global__ void k_scatter(const int* __restrict__ ei, int E) {
    int e = blockIdx.x * blockDim.x + threadIdx.x;
    if (e < E) {
        int d = ei[E + e];
        int pos = atomicAdd(&g_fill[d], 1);
        g_col[pos] = ei[e];
    }
}

// ---------------- agg conv1: gather fp16 (F=128) ----------------
__global__ void k_agg_x_h(int src_sel, int dst_sel) {
    const __half* in = selbuf(src_sel);
    __half* out = selbuf(dst_sel);
    const int wid = (blockIdx.x * blockDim.x + threadIdx.x) >> 5;
    if (wid >= NNODES) return;
    const int lane = threadIdx.x & 31;
    const int coff = lane * 4;

    float acc[4] = {0.f, 0.f, 0.f, 0.f};
    const int beg = g_rowptr[wid];
    const int end = g_rowptr[wid + 1];
    for (int base = beg; base < end; base += 32) {
        const int nrem = end - base;
        int idx = 0;
        float w = 0.f;
        if (lane < nrem) {
            idx = g_col[base + lane];
            w = g_dinv[idx];
        }
        const int m = nrem < 32 ? nrem : 32;
        int j = 0;
        for (; j + 2 <= m; j += 2) {
            const int s0 = __shfl_sync(0xffffffffu, idx, j);
            const int s1 = __shfl_sync(0xffffffffu, idx, j + 1);
            const float w0 = __shfl_sync(0xffffffffu, w, j);
            const float w1 = __shfl_sync(0xffffffffu, w, j + 1);
            uint2 v0 = *reinterpret_cast<const uint2*>(in + (size_t)s0 * FIN + coff);
            uint2 v1 = *reinterpret_cast<const uint2*>(in + (size_t)s1 * FIN + coff);
            const __half2* h0 = reinterpret_cast<const __half2*>(&v0);
            const __half2* h1 = reinterpret_cast<const __half2*>(&v1);
#pragma unroll
            for (int k = 0; k < 2; k++) {
                float2 a = __half22float2(h0[k]);
                float2 b = __half22float2(h1[k]);
                acc[2 * k] += w0 * a.x + w1 * b.x;
                acc[2 * k + 1] += w0 * a.y + w1 * b.y;
            }
        }
        for (; j < m; j++) {
            const int s = __shfl_sync(0xffffffffu, idx, j);
            const float ww = __shfl_sync(0xffffffffu, w, j);
            uint2 v = *reinterpret_cast<const uint2*>(in + (size_t)s * FIN + coff);
            const __half2* h = reinterpret_cast<const __half2*>(&v);
#pragma unroll
            for (int k = 0; k < 2; k++) {
                float2 a = __half22float2(h[k]);
                acc[2 * k] += ww * a.x;
                acc[2 * k + 1] += ww * a.y;
            }
        }
    }
    const float di = g_dinv[wid];
    {
        uint2 v = *reinterpret_cast<const uint2*>(in + (size_t)wid * FIN + coff);
        const __half2* h = reinterpret_cast<const __half2*>(&v);
#pragma unroll
        for (int k = 0; k < 2; k++) {
            float2 a = __half22float2(h[k]);
            acc[2 * k] += di * a.x;
            acc[2 * k + 1] += di * a.y;
        }
    }
    uint2 o;
    __half2* oh = reinterpret_cast<__half2*>(&o);
    oh[0] = __floats2half2_rn(di * acc[0], di * acc[1]);
    oh[1] = __floats2half2_rn(di * acc[2], di * acc[3]);
    *reinterpret_cast<uint2*>(out + (size_t)wid * FIN + coff) = o;
}

// ---------------- agg mid layers: gather half F=256, +bias+relu ----------------
__global__ void k_agg_h256(int src_sel, int dst_sel, const float* __restrict__ bias) {
    const __half* in = selbuf(src_sel);
    __half* out = selbuf(dst_sel);
    const int wid = (blockIdx.x * blockDim.x + threadIdx.x) >> 5;
    if (wid >= NNODES) return;
    const int lane = threadIdx.x & 31;
    const int coff = lane * 8;

    float acc[8];
#pragma unroll
    for (int i = 0; i < 8; i++) acc[i] = 0.f;

    const int beg = g_rowptr[wid];
    const int end = g_rowptr[wid + 1];
    for (int base = beg; base < end; base += 32) {
        const int nrem = end - base;
        int idx = 0;
        float w = 0.f;
        if (lane < nrem) {
            idx = g_col[base + lane];
            w = g_dinv[idx];
        }
        const int m = nrem < 32 ? nrem : 32;
        int j = 0;
        for (; j + 2 <= m; j += 2) {
            const int s0 = __shfl_sync(0xffffffffu, idx, j);
            const int s1 = __shfl_sync(0xffffffffu, idx, j + 1);
            const float w0 = __shfl_sync(0xffffffffu, w, j);
            const float w1 = __shfl_sync(0xffffffffu, w, j + 1);
            uint4 v0 = *reinterpret_cast<const uint4*>(in + (size_t)s0 * HID + coff);
            uint4 v1 = *reinterpret_cast<const uint4*>(in + (size_t)s1 * HID + coff);
            float f0[8], f1[8];
            h8_to_f8(v0, f0);
            h8_to_f8(v1, f1);
#pragma unroll
            for (int i = 0; i < 8; i++) acc[i] += w0 * f0[i] + w1 * f1[i];
        }
        for (; j < m; j++) {
            const int s = __shfl_sync(0xffffffffu, idx, j);
            const float ww = __shfl_sync(0xffffffffu, w, j);
            uint4 v = *reinterpret_cast<const uint4*>(in + (size_t)s * HID + coff);
            float f[8];
            h8_to_f8(v, f);
#pragma unroll
            for (int i = 0; i < 8; i++) acc[i] += ww * f[i];
        }
    }
    const float di = g_dinv[wid];
    {
        uint4 v = *reinterpret_cast<const uint4*>(in + (size_t)wid * HID + coff);
        float f[8];
        h8_to_f8(v, f);
#pragma unroll
        for (int i = 0; i < 8; i++) acc[i] += di * f[i];
    }
    float r[8];
#pragma unroll
    for (int i = 0; i < 8; i++) {
        r[i] = fmaxf(di * acc[i] + bias[coff + i], 0.f);
    }
    *reinterpret_cast<uint4*>(out + (size_t)wid * HID + coff) = f8_to_h8(r);
}

// ---------------- final: gather half F=40, +bias, log_softmax ----------------
__global__ void k_agg40_lsm(int src_sel, float* __restrict__ out,
                            const float* __restrict__ bias) {
    const __half* in = selbuf(src_sel);
    const int wid = (blockIdx.x * blockDim.x + threadIdx.x) >> 5;
    if (wid >= NNODES) return;
    const int lane = threadIdx.x & 31;
    const bool has2 = lane < (NCLS - 32);

    float a0 = 0.f, a1 = 0.f;
    const int beg = g_rowptr[wid];
    const int end = g_rowptr[wid + 1];
    for (int base = beg; base < end; base += 32) {
        const int nrem = end - base;
        int idx = 0;
        float w = 0.f;
        if (lane < nrem) {
            idx = g_col[base + lane];
            w = g_dinv[idx];
        }
        const int m = nrem < 32 ? nrem : 32;
        for (int j = 0; j < m; j++) {
            const int s = __shfl_sync(0xffffffffu, idx, j);
            const float ww = __shfl_sync(0xffffffffu, w, j);
            a0 += ww * __half2float(in[(size_t)s * NCLS + lane]);
            if (has2) a1 += ww * __half2float(in[(size_t)s * NCLS + 32 + lane]);
        }
    }
    const float di = g_dinv[wid];
    a0 += di * __half2float(in[(size_t)wid * NCLS + lane]);
    if (has2) a1 += di * __half2float(in[(size_t)wid * NCLS + 32 + lane]);

    a0 = di * a0 + bias[lane];
    a1 = has2 ? (di * a1 + bias[32 + lane]) : -INFINITY;

    float mx = fmaxf(a0, a1);
#pragma unroll
    for (int off = 16; off; off >>= 1) mx = fmaxf(mx, __shfl_xor_sync(0xffffffffu, mx, off));
    float se = expf(a0 - mx) + (has2 ? expf(a1 - mx) : 0.f);
#pragma unroll
    for (int off = 16; off; off >>= 1) se += __shfl_xor_sync(0xffffffffu, se, off);
    const float lse = logf(se) + mx;

    out[(size_t)wid * NCLS + lane] = a0 - lse;
    if (has2) out[(size_t)wid * NCLS + 32 + lane] = a1 - lse;
}

// ---------------- double-buffered smem tensor-core GEMM ----------------
// Block 128M x 128N, 256 threads, 8 warps (2M x 4N), warp tile 64x32.
// BK=32 chunks; smem double-buffered (41KB) -> ONE barrier per chunk;
// next chunk prefetched into registers during compute.
template <int K, bool EPI>
__global__ __launch_bounds__(256) void k_gemm_mma4(int src_sel, int wsel,
                                                   const float* __restrict__ bias, int dst_sel) {
    const __half* A = selbuf(src_sel);
    __half* C = selbuf(dst_sel);
    const __half* WT = (wsel == 1) ? g_W1T : (wsel == 2) ? g_W2T : g_W3T;

    constexpr int BK = 32, LDSW = BK + 8;   // 40 halfs (80B) row stride
    constexpr int T = K / BK;
    __shared__ __half As[2][128][LDSW];
    __shared__ __half Bs[2][128][LDSW];

    const int tid = threadIdx.x;
    const int wid = tid >> 5;
    const int lane = tid & 31;
    const int gid = lane >> 2;
    const int tig = lane & 3;
    const int m0 = blockIdx.x * 128;
    const int n0 = blockIdx.y * 128;
    const int mb = (wid & 1) * 64;
    const int nb = (wid >> 1) * 32;

    float c[4][4][4];
#pragma unroll
    for (int i = 0; i < 4; i++)
#pragma unroll
        for (int j = 0; j < 4; j++)
#pragma unroll
            for (int q = 0; q < 4; q++) c[i][j][q] = 0.f;

    uint4 ra[2], rb[2];

    auto load_regs = [&](int t) {
        const int kc = t * BK;
#pragma unroll
        for (int l = 0; l < 2; l++) {
            const int idx = tid + l * 256;   // 0..511
            const int r = idx >> 2;          // 0..127
            const int c8 = idx & 3;          // 4 uint4 per 32-halfs row
            ra[l] = *reinterpret_cast<const uint4*>(A + (size_t)(m0 + r) * K + kc + c8 * 8);
            rb[l] = *reinterpret_cast<const uint4*>(WT + (size_t)(n0 + r) * K + kc + c8 * 8);
        }
    };
    auto store_smem = [&](int buf) {
#pragma unroll
        for (int l = 0; l < 2; l++) {
            const int idx = tid + l * 256;
            const int r = idx >> 2;
            const int c8 = idx & 3;
            *reinterpret_cast<uint4*>(&As[buf][r][c8 * 8]) = ra[l];
            *reinterpret_cast<uint4*>(&Bs[buf][r][c8 * 8]) = rb[l];
        }
    };

    load_regs(0);
    store_smem(0);
    __syncthreads();

    for (int t = 0; t < T; t++) {
        const int cur = t & 1;
        if (t + 1 < T) load_regs(t + 1);
#pragma unroll
        for (int kg = 0; kg < BK / 16; kg++) {
            const int kk = kg * 16;
            unsigned a[4][4];
#pragma unroll
            for (int i = 0; i < 4; i++) {
                unsigned addr = (unsigned)__cvta_generic_to_shared(
                    &As[cur][mb + i * 16 + (lane & 15)][kk + (lane >> 4) * 8]);
                asm volatile("ldmatrix.sync.aligned.m8n8.x4.shared.b16 {%0,%1,%2,%3}, [%4];"
                             : "=r"(a[i][0]), "=r"(a[i][1]), "=r"(a[i][2]), "=r"(a[i][3])
                             : "r"(addr));
            }
#pragma unroll
            for (int j = 0; j < 4; j++) {
                const uint2 b = *reinterpret_cast<const uint2*>(
                    &Bs[cur][nb + j * 8 + gid][kk + tig * 4]);
#pragma unroll
                for (int i = 0; i < 4; i++) {
                    asm volatile(
                        "mma.sync.aligned.m16n8k16.row.col.f32.f16.f16.f32 "
                        "{%0,%1,%2,%3}, {%4,%5,%6,%7}, {%8,%9}, {%0,%1,%2,%3};"
                        : "+f"(c[i][j][0]), "+f"(c[i][j][1]), "+f"(c[i][j][2]), "+f"(c[i][j][3])
                        : "r"(a[i][0]), "r"(a[i][1]), "r"(a[i][2]), "r"(a[i][3]),
                          "r"(b.x), "r"(b.y));
                }
            }
        }
        if (t + 1 < T) {
            store_smem((t + 1) & 1);   // other buffer: safe, prior barrier drained its readers
            __syncthreads();
        }
    }

#pragma unroll
    for (int i = 0; i < 4; i++) {
        const int r0 = m0 + mb + i * 16 + gid;
#pragma unroll
        for (int j = 0; j < 4; j++) {
            const int col = n0 + nb + j * 8 + 2 * tig;
            float v0 = c[i][j][0], v1 = c[i][j][1], v2 = c[i][j][2], v3 = c[i][j][3];
            if (EPI) {
                const float bz0 = bias[col];
                const float bz1 = bias[col + 1];
                v0 = fmaxf(v0 + bz0, 0.f); v1 = fmaxf(v1 + bz1, 0.f);
                v2 = fmaxf(v2 + bz0, 0.f); v3 = fmaxf(v3 + bz1, 0.f);
            }
            if (r0 < NNODES)
                *reinterpret_cast<__half2*>(C + (size_t)r0 * HID + col) = __floats2half2_rn(v0, v1);
            if (r0 + 8 < NNODES)
                *reinterpret_cast<__half2*>(C + (size_t)(r0 + 8) * HID + col) = __floats2half2_rn(v2, v3);
        }
    }
}

// ---------------- mma small GEMM: C_half[M,40] = A_half[M,256] @ W4 ----------------
__global__ __launch_bounds__(256) void k_gemm_small_mma(int src_sel, int dst_sel) {
    const __half* A = selbuf(src_sel);
    __half* C = selbuf(dst_sel);
    constexpr int K = HID;

    const int tid = threadIdx.x;
    const int wid = tid >> 5;
    const int lane = tid & 31;
    const int gid = lane >> 2;
    const int tig = lane & 3;
    const int mbase = blockIdx.x * 256 + wid * 32;

    float c[2][5][4];
#pragma unroll
    for (int i = 0; i < 2; i++)
#pragma unroll
        for (int j = 0; j < 5; j++)
#pragma unroll
            for (int q = 0; q < 4; q++) c[i][j][q] = 0.f;

#pragma unroll 4
    for (int kg = 0; kg < K / 16; kg++) {
        const int k0 = kg * 16;
        unsigned a[2][4];
#pragma unroll
        for (int i = 0; i < 2; i++) {
            const __half* ap = A + (size_t)(mbase + i * 16 + gid) * K + k0 + 2 * tig;
            a[i][0] = *reinterpret_cast<const unsigned*>(ap);
            a[i][1] = *reinterpret_cast<const unsigned*>(ap + 8 * K);
            a[i][2] = *reinterpret_cast<const unsigned*>(ap + 8);
            a[i][3] = *reinterpret_cast<const unsigned*>(ap + 8 * K + 8);
        }
#pragma unroll
        for (int j = 0; j < 5; j++) {
            const uint2 b = *reinterpret_cast<const uint2*>(
                g_W4T + (size_t)(j * 8 + gid) * K + k0 + tig * 4);
#pragma unroll
            for (int i = 0; i < 2; i++) {
                asm volatile(
                    "mma.sync.aligned.m16n8k16.row.col.f32.f16.f16.f32 "
                    "{%0,%1,%2,%3}, {%4,%5,%6,%7}, {%8,%9}, {%0,%1,%2,%3};"
                    : "+f"(c[i][j][0]), "+f"(c[i][j][1]), "+f"(c[i][j][2]), "+f"(c[i][j][3])
                    : "r"(a[i][0]), "r"(a[i][1]), "r"(a[i][2]), "r"(a[i][3]),
                      "r"(b.x), "r"(b.y));
            }
        }
    }

#pragma unroll
    for (int i = 0; i < 2; i++) {
        const int r0 = mbase + i * 16 + gid;
#pragma unroll
        for (int j = 0; j < 5; j++) {
            const int col = j * 8 + 2 * tig;
            if (r0 < NNODES)
                *reinterpret_cast<__half2*>(C + (size_t)r0 * NCLS + col) =
                    __floats2half2_rn(c[i][j][0], c[i][j][1]);
            if (r0 + 8 < NNODES)
                *reinterpret_cast<__half2*>(C + (size_t)(r0 + 8) * NCLS + col) =
                    __floats2half2_rn(c[i][j][2], c[i][j][3]);
        }
    }
}

// ---------------- launch ----------------
extern "C" void kernel_launch(void* const* d_in, const int* in_sizes, int n_in,
                              void* d_out, int out_size) {
    const float* x = (const float*)d_in[0];
    const int* ei = (const int*)d_in[1];
    const float* W1 = (const float*)d_in[2];
    const float* b1 = (const float*)d_in[3];
    const float* W2 = (const float*)d_in[4];
    const float* b2 = (const float*)d_in[5];
    const float* W3 = (const float*)d_in[6];
    const float* b3 = (const float*)d_in[7];
    const float* W4 = (const float*)d_in[8];
    const float* b4 = (const float*)d_in[9];
    float* out = (float*)d_out;
    const int E = in_sizes[1] / 2;

    k_prep<<<(NXCONV + 255) / 256, 256>>>(x, W1, W2, W3, W4, 1);  // xconv -> B, hist=0, WTs
    k_hist<<<(E + 255) / 256, 256>>>(ei, E);
    k_scan_s1<<<NBLK256, 256>>>();
    k_scan_s2<<<1, 512>>>();
    k_scan_s3<<<NBLK256, 256>>>(E);
    k_scatter<<<(E + 255) / 256, 256>>>(ei, E);

    const int AGG_BLOCKS = (NNODES + 7) / 8;
    const dim3 GG(NPAD / 128, 2);
    const int GS = NPAD / 256;

    // conv1
    k_agg_x_h<<<AGG_BLOCKS, 256>>>(1, 0);                     // B -> A
    k_gemm_mma4<128, true><<<GG, 256>>>(0, 1, b1, 1);         // A -> B

    // conv2
    k_gemm_mma4<256, false><<<GG, 256>>>(1, 2, nullptr, 0);   // B -> A
    k_agg_h256<<<AGG_BLOCKS, 256>>>(0, 1, b2);                // A -> B

    // conv3 (reuses W2/b2)
    k_gemm_mma4<256, false><<<GG, 256>>>(1, 2, nullptr, 0);
    k_agg_h256<<<AGG_BLOCKS, 256>>>(0, 1, b2);

    // conv4
    k_gemm_mma4<256, false><<<GG, 256>>>(1, 3, nullptr, 0);
    k_agg_h256<<<AGG_BLOCKS, 256>>>(0, 1, b3);

    // conv5
    k_gemm_small_mma<<<GS, 256>>>(1, 0);                      // B -> A
    k_agg40_lsm<<<AGG_BLOCKS, 256>>>(0, out, b4);
}

// round 14
// speedup vs baseline: 1.0521x; 1.0521x over previous
#include <cuda_runtime.h>
#include <cuda_fp16.h>
#include <math.h>

#define NNODES 100000
#define NPAD   100096
#define FIN    128
#define HID    256
#define NCLS   40
#define EMAX   1600000
#define NBLK256 ((NNODES + 255) / 256)   // 391
#define NXCONV  (NNODES * (FIN / 4))     // 3.2M float4 elements

// ---------------- scratch ----------------
__device__ __half g_bufA[(size_t)NPAD * HID];
__device__ __half g_bufB[(size_t)NPAD * HID];
__device__ __half g_W1T[256 * 128];
__device__ __half g_W2T[256 * 256];
__device__ __half g_W3T[256 * 256];
__device__ __half g_W4T[40 * 256];
__device__ float g_dinv[NNODES];
__device__ int   g_hist[NNODES];
__device__ int   g_rowptr[NNODES + 1];
__device__ int   g_fill[NNODES];
__device__ int   g_col[EMAX];
__device__ int   g_bsum[NBLK256];
__device__ int   g_boff[NBLK256];

__device__ __forceinline__ __half* selbuf(int s) { return s ? g_bufB : g_bufA; }

__device__ __forceinline__ void h8_to_f8(uint4 v, float* f) {
    const __half2* h = reinterpret_cast<const __half2*>(&v);
#pragma unroll
    for (int k = 0; k < 4; k++) {
        float2 t = __half22float2(h[k]);
        f[2 * k] = t.x;
        f[2 * k + 1] = t.y;
    }
}
__device__ __forceinline__ uint4 f8_to_h8(const float* f) {
    uint4 o;
    __half2* h = reinterpret_cast<__half2*>(&o);
#pragma unroll
    for (int k = 0; k < 4; k++) h[k] = __floats2half2_rn(f[2 * k], f[2 * k + 1]);
    return o;
}

// ---------------- fused prep: xconv + hist-init + weight conversion ----------------
__global__ void k_prep(const float* __restrict__ x,
                       const float* __restrict__ W1, const float* __restrict__ W2,
                       const float* __restrict__ W3, const float* __restrict__ W4,
                       int xdst_sel) {
    const int i = blockIdx.x * blockDim.x + threadIdx.x;
    if (i < NXCONV) {
        float4 v = reinterpret_cast<const float4*>(x)[i];
        uint2 o;
        __half2* oh = reinterpret_cast<__half2*>(&o);
        oh[0] = __floats2half2_rn(v.x, v.y);
        oh[1] = __floats2half2_rn(v.z, v.w);
        reinterpret_cast<uint2*>(selbuf(xdst_sel))[i] = o;
    }
    if (i < NNODES) g_hist[i] = 0;
    if (i < 256 * 256) {
        int n = i >> 8, k = i & 255;
        int ko = (k & ~15) + 2 * ((k >> 2) & 3) + (k & 1) + (((k >> 1) & 1) << 3);
        g_W2T[n * 256 + k] = __float2half(W2[ko * 256 + n]);
        g_W3T[n * 256 + k] = __float2half(W3[ko * 256 + n]);
    }
    if (i < 256 * 128) {
        int n = i >> 7, k = i & 127;
        int ko = (k & ~15) + 2 * ((k >> 2) & 3) + (k & 1) + (((k >> 1) & 1) << 3);
        g_W1T[n * 128 + k] = __float2half(W1[ko * 256 + n]);
    }
    if (i < 40 * 256) {
        int n = i >> 8, k = i & 255;
        int ko = (k & ~15) + 2 * ((k >> 2) & 3) + (k & 1) + (((k >> 1) & 1) << 3);
        g_W4T[n * 256 + k] = __float2half(W4[ko * NCLS + n]);
    }
}

// ---------------- CSR build ----------------
__global__ void k_hist(const int* __restrict__ ei, int E) {
    int e = blockIdx.x * blockDim.x + threadIdx.x;
    if (e < E) atomicAdd(&g_hist[ei[E + e]], 1);
}

__global__ void k_scan_s1() {
    __shared__ int s[256];
    const int t = threadIdx.x;
    const int i = blockIdx.x * 256 + t;
    s[t] = (i < NNODES) ? g_hist[i] : 0;
    __syncthreads();
    for (int off = 128; off; off >>= 1) {
        if (t < off) s[t] += s[t + off];
        __syncthreads();
    }
    if (t == 0) g_bsum[blockIdx.x] = s[0];
}

__global__ void k_scan_s2() {
    __shared__ int s[512];
    const int t = threadIdx.x;
    s[t] = (t < NBLK256) ? g_bsum[t] : 0;
    __syncthreads();
    for (int off = 1; off < 512; off <<= 1) {
        int v = (t >= off) ? s[t - off] : 0;
        __syncthreads();
        s[t] += v;
        __syncthreads();
    }
    if (t < NBLK256) g_boff[t] = (t == 0) ? 0 : s[t - 1];
}

__global__ void k_scan_s3(int E) {
    __shared__ int s[256];
    const int t = threadIdx.x;
    const int i = blockIdx.x * 256 + t;
    const int h = (i < NNODES) ? g_hist[i] : 0;
    s[t] = h;
    __syncthreads();
    for (int off = 1; off < 256; off <<= 1) {
        int v = (t >= off) ? s[t - off] : 0;
        __syncthreads();
        s[t] += v;
        __syncthreads();
    }
    if (i < NNODES) {
        const int ex = g_boff[blockIdx.x] + s[t] - h;
        g_rowptr[i] = ex;
        g_fill[i] = ex;
        g_dinv[i] = rsqrtf((float)(h + 1));
    }
    if (i == 0) g_rowptr[NNODES] = E;
}

__global__ void k_scatter(const int* __restrict__ ei, int E) {
    int e = blockIdx.x * blockDim.x + threadIdx.x;
    if (e < E) {
        int d = ei[E + e];
        int pos = atomicAdd(&g_fill[d], 1);
        g_col[pos] = ei[e];
    }
}

// ---------------- agg conv1: gather fp16 (F=128) ----------------
__global__ void k_agg_x_h(int src_sel, int dst_sel) {
    const __half* in = selbuf(src_sel);
    __half* out = selbuf(dst_sel);
    const int wid = (blockIdx.x * blockDim.x + threadIdx.x) >> 5;
    if (wid >= NNODES) return;
    const int lane = threadIdx.x & 31;
    const int coff = lane * 4;

    float acc[4] = {0.f, 0.f, 0.f, 0.f};
    const int beg = g_rowptr[wid];
    const int end = g_rowptr[wid + 1];
    for (int base = beg; base < end; base += 32) {
        const int nrem = end - base;
        int idx = 0;
        float w = 0.f;
        if (lane < nrem) {
            idx = g_col[base + lane];
            w = g_dinv[idx];
        }
        const int m = nrem < 32 ? nrem : 32;
        int j = 0;
        for (; j + 2 <= m; j += 2) {
            const int s0 = __shfl_sync(0xffffffffu, idx, j);
            const int s1 = __shfl_sync(0xffffffffu, idx, j + 1);
            const float w0 = __shfl_sync(0xffffffffu, w, j);
            const float w1 = __shfl_sync(0xffffffffu, w, j + 1);
            uint2 v0 = *reinterpret_cast<const uint2*>(in + (size_t)s0 * FIN + coff);
            uint2 v1 = *reinterpret_cast<const uint2*>(in + (size_t)s1 * FIN + coff);
            const __half2* h0 = reinterpret_cast<const __half2*>(&v0);
            const __half2* h1 = reinterpret_cast<const __half2*>(&v1);
#pragma unroll
            for (int k = 0; k < 2; k++) {
                float2 a = __half22float2(h0[k]);
                float2 b = __half22float2(h1[k]);
                acc[2 * k] += w0 * a.x + w1 * b.x;
                acc[2 * k + 1] += w0 * a.y + w1 * b.y;
            }
        }
        for (; j < m; j++) {
            const int s = __shfl_sync(0xffffffffu, idx, j);
            const float ww = __shfl_sync(0xffffffffu, w, j);
            uint2 v = *reinterpret_cast<const uint2*>(in + (size_t)s * FIN + coff);
            const __half2* h = reinterpret_cast<const __half2*>(&v);
#pragma unroll
            for (int k = 0; k < 2; k++) {
                float2 a = __half22float2(h[k]);
                acc[2 * k] += ww * a.x;
                acc[2 * k + 1] += ww * a.y;
            }
        }
    }
    const float di = g_dinv[wid];
    {
        uint2 v = *reinterpret_cast<const uint2*>(in + (size_t)wid * FIN + coff);
        const __half2* h = reinterpret_cast<const __half2*>(&v);
#pragma unroll
        for (int k = 0; k < 2; k++) {
            float2 a = __half22float2(h[k]);
            acc[2 * k] += di * a.x;
            acc[2 * k + 1] += di * a.y;
        }
    }
    uint2 o;
    __half2* oh = reinterpret_cast<__half2*>(&o);
    oh[0] = __floats2half2_rn(di * acc[0], di * acc[1]);
    oh[1] = __floats2half2_rn(di * acc[2], di * acc[3]);
    *reinterpret_cast<uint2*>(out + (size_t)wid * FIN + coff) = o;
}

// ---------------- agg mid layers: gather half F=256, +bias+relu ----------------
__global__ void k_agg_h256(int src_sel, int dst_sel, const float* __restrict__ bias) {
    const __half* in = selbuf(src_sel);
    __half* out = selbuf(dst_sel);
    const int wid = (blockIdx.x * blockDim.x + threadIdx.x) >> 5;
    if (wid >= NNODES) return;
    const int lane = threadIdx.x & 31;
    const int coff = lane * 8;

    float acc[8];
#pragma unroll
    for (int i = 0; i < 8; i++) acc[i] = 0.f;

    const int beg = g_rowptr[wid];
    const int end = g_rowptr[wid + 1];
    for (int base = beg; base < end; base += 32) {
        const int nrem = end - base;
        int idx = 0;
        float w = 0.f;
        if (lane < nrem) {
            idx = g_col[base + lane];
            w = g_dinv[idx];
        }
        const int m = nrem < 32 ? nrem : 32;
        int j = 0;
        for (; j + 2 <= m; j += 2) {
            const int s0 = __shfl_sync(0xffffffffu, idx, j);
            const int s1 = __shfl_sync(0xffffffffu, idx, j + 1);
            const float w0 = __shfl_sync(0xffffffffu, w, j);
            const float w1 = __shfl_sync(0xffffffffu, w, j + 1);
            uint4 v0 = *reinterpret_cast<const uint4*>(in + (size_t)s0 * HID + coff);
            uint4 v1 = *reinterpret_cast<const uint4*>(in + (size_t)s1 * HID + coff);
            float f0[8], f1[8];
            h8_to_f8(v0, f0);
            h8_to_f8(v1, f1);
#pragma unroll
            for (int i = 0; i < 8; i++) acc[i] += w0 * f0[i] + w1 * f1[i];
        }
        for (; j < m; j++) {
            const int s = __shfl_sync(0xffffffffu, idx, j);
            const float ww = __shfl_sync(0xffffffffu, w, j);
            uint4 v = *reinterpret_cast<const uint4*>(in + (size_t)s * HID + coff);
            float f[8];
            h8_to_f8(v, f);
#pragma unroll
            for (int i = 0; i < 8; i++) acc[i] += ww * f[i];
        }
    }
    const float di = g_dinv[wid];
    {
        uint4 v = *reinterpret_cast<const uint4*>(in + (size_t)wid * HID + coff);
        float f[8];
        h8_to_f8(v, f);
#pragma unroll
        for (int i = 0; i < 8; i++) acc[i] += di * f[i];
    }
    float r[8];
#pragma unroll
    for (int i = 0; i < 8; i++) {
        r[i] = fmaxf(di * acc[i] + bias[coff + i], 0.f);
    }
    *reinterpret_cast<uint4*>(out + (size_t)wid * HID + coff) = f8_to_h8(r);
}

// ---------------- final: gather half F=40, +bias, log_softmax ----------------
__global__ void k_agg40_lsm(int src_sel, float* __restrict__ out,
                            const float* __restrict__ bias) {
    const __half* in = selbuf(src_sel);
    const int wid = (blockIdx.x * blockDim.x + threadIdx.x) >> 5;
    if (wid >= NNODES) return;
    const int lane = threadIdx.x & 31;
    const bool has2 = lane < (NCLS - 32);

    float a0 = 0.f, a1 = 0.f;
    const int beg = g_rowptr[wid];
    const int end = g_rowptr[wid + 1];
    for (int base = beg; base < end; base += 32) {
        const int nrem = end - base;
        int idx = 0;
        float w = 0.f;
        if (lane < nrem) {
            idx = g_col[base + lane];
            w = g_dinv[idx];
        }
        const int m = nrem < 32 ? nrem : 32;
        for (int j = 0; j < m; j++) {
            const int s = __shfl_sync(0xffffffffu, idx, j);
            const float ww = __shfl_sync(0xffffffffu, w, j);
            a0 += ww * __half2float(in[(size_t)s * NCLS + lane]);
            if (has2) a1 += ww * __half2float(in[(size_t)s * NCLS + 32 + lane]);
        }
    }
    const float di = g_dinv[wid];
    a0 += di * __half2float(in[(size_t)wid * NCLS + lane]);
    if (has2) a1 += di * __half2float(in[(size_t)wid * NCLS + 32 + lane]);

    a0 = di * a0 + bias[lane];
    a1 = has2 ? (di * a1 + bias[32 + lane]) : -INFINITY;

    float mx = fmaxf(a0, a1);
#pragma unroll
    for (int off = 16; off; off >>= 1) mx = fmaxf(mx, __shfl_xor_sync(0xffffffffu, mx, off));
    float se = expf(a0 - mx) + (has2 ? expf(a1 - mx) : 0.f);
#pragma unroll
    for (int off = 16; off; off >>= 1) se += __shfl_xor_sync(0xffffffffu, se, off);
    const float lse = logf(se) + mx;

    out[(size_t)wid * NCLS + lane] = a0 - lse;
    if (has2) out[(size_t)wid * NCLS + 32 + lane] = a1 - lse;
}

// ---------------- pipelined smem tensor-core GEMM (R11 config — best known) ----------------
// Block 128M x 128N, 256 threads, 8 warps (2M x 4N), warp tile 64x32.
// BK=64 chunk staged in smem; NEXT chunk LDG'd into registers during compute.
template <int K, bool EPI>
__global__ __launch_bounds__(256) void k_gemm_mma3(int src_sel, int wsel,
                                                   const float* __restrict__ bias, int dst_sel) {
    const __half* A = selbuf(src_sel);
    __half* C = selbuf(dst_sel);
    const __half* WT = (wsel == 1) ? g_W1T : (wsel == 2) ? g_W2T : g_W3T;

    constexpr int BK = 64, LDSW = BK + 8;   // 72 halfs per row
    constexpr int T = K / BK;
    __shared__ __half As[128][LDSW];
    __shared__ __half Bs[128][LDSW];

    const int tid = threadIdx.x;
    const int wid = tid >> 5;
    const int lane = tid & 31;
    const int gid = lane >> 2;
    const int tig = lane & 3;
    const int m0 = blockIdx.x * 128;
    const int n0 = blockIdx.y * 128;
    const int mb = (wid & 1) * 64;
    const int nb = (wid >> 1) * 32;

    float c[4][4][4];
#pragma unroll
    for (int i = 0; i < 4; i++)
#pragma unroll
        for (int j = 0; j < 4; j++)
#pragma unroll
            for (int q = 0; q < 4; q++) c[i][j][q] = 0.f;

    uint4 ra[4], rb[4];

    auto load_regs = [&](int t) {
        const int kc = t * BK;
#pragma unroll
        for (int l = 0; l < 4; l++) {
            const int idx = tid + l * 256;   // 0..1023
            const int r = idx >> 3;
            const int c8 = idx & 7;
            ra[l] = *reinterpret_cast<const uint4*>(A + (size_t)(m0 + r) * K + kc + c8 * 8);
            rb[l] = *reinterpret_cast<const uint4*>(WT + (size_t)(n0 + r) * K + kc + c8 * 8);
        }
    };
    auto store_smem = [&]() {
#pragma unroll
        for (int l = 0; l < 4; l++) {
            const int idx = tid + l * 256;
            const int r = idx >> 3;
            const int c8 = idx & 7;
            *reinterpret_cast<uint4*>(&As[r][c8 * 8]) = ra[l];
            *reinterpret_cast<uint4*>(&Bs[r][c8 * 8]) = rb[l];
        }
    };

    load_regs(0);
    store_smem();
    __syncthreads();

    for (int t = 0; t < T; t++) {
        if (t + 1 < T) load_regs(t + 1);
#pragma unroll
        for (int kg = 0; kg < BK / 16; kg++) {
            const int kk = kg * 16;
            unsigned a[4][4];
#pragma unroll
            for (int i = 0; i < 4; i++) {
                unsigned addr = (unsigned)__cvta_generic_to_shared(
                    &As[mb + i * 16 + (lane & 15)][kk + (lane >> 4) * 8]);
                asm volatile("ldmatrix.sync.aligned.m8n8.x4.shared.b16 {%0,%1,%2,%3}, [%4];"
                             : "=r"(a[i][0]), "=r"(a[i][1]), "=r"(a[i][2]), "=r"(a[i][3])
                             : "r"(addr));
            }
#pragma unroll
            for (int j = 0; j < 4; j++) {
                const uint2 b = *reinterpret_cast<const uint2*>(&Bs[nb + j * 8 + gid][kk + tig * 4]);
#pragma unroll
                for (int i = 0; i < 4; i++) {
                    asm volatile(
                        "mma.sync.aligned.m16n8k16.row.col.f32.f16.f16.f32 "
                        "{%0,%1,%2,%3}, {%4,%5,%6,%7}, {%8,%9}, {%0,%1,%2,%3};"
                        : "+f"(c[i][j][0]), "+f"(c[i][j][1]), "+f"(c[i][j][2]), "+f"(c[i][j][3])
                        : "r"(a[i][0]), "r"(a[i][1]), "r"(a[i][2]), "r"(a[i][3]),
                          "r"(b.x), "r"(b.y));
                }
            }
        }
        if (t + 1 < T) {
            __syncthreads();
            store_smem();
            __syncthreads();
        }
    }

#pragma unroll
    for (int i = 0; i < 4; i++) {
        const int r0 = m0 + mb + i * 16 + gid;
#pragma unroll
        for (int j = 0; j < 4; j++) {
            const int col = n0 + nb + j * 8 + 2 * tig;
            float v0 = c[i][j][0], v1 = c[i][j][1], v2 = c[i][j][2], v3 = c[i][j][3];
            if (EPI) {
                const float bz0 = bias[col];
                const float bz1 = bias[col + 1];
                v0 = fmaxf(v0 + bz0, 0.f); v1 = fmaxf(v1 + bz1, 0.f);
                v2 = fmaxf(v2 + bz0, 0.f); v3 = fmaxf(v3 + bz1, 0.f);
            }
            if (r0 < NNODES)
                *reinterpret_cast<__half2*>(C + (size_t)r0 * HID + col) = __floats2half2_rn(v0, v1);
            if (r0 + 8 < NNODES)
                *reinterpret_cast<__half2*>(C + (size_t)(r0 + 8) * HID + col) = __floats2half2_rn(v2, v3);
        }
    }
}

// ---------------- mma small GEMM: C_half[M,40] = A_half[M,256] @ W4 ----------------
__global__ __launch_bounds__(256) void k_gemm_small_mma(int src_sel, int dst_sel) {
    const __half* A = selbuf(src_sel);
    __half* C = selbuf(dst_sel);
    constexpr int K = HID;

    const int tid = threadIdx.x;
    const int wid = tid >> 5;
    const int lane = tid & 31;
    const int gid = lane >> 2;
    const int tig = lane & 3;
    const int mbase = blockIdx.x * 256 + wid * 32;

    float c[2][5][4];
#pragma unroll
    for (int i = 0; i < 2; i++)
#pragma unroll
        for (int j = 0; j < 5; j++)
#pragma unroll
            for (int q = 0; q < 4; q++) c[i][j][q] = 0.f;

#pragma unroll 4
    for (int kg = 0; kg < K / 16; kg++) {
        const int k0 = kg * 16;
        unsigned a[2][4];
#pragma unroll
        for (int i = 0; i < 2; i++) {
            const __half* ap = A + (size_t)(mbase + i * 16 + gid) * K + k0 + 2 * tig;
            a[i][0] = *reinterpret_cast<const unsigned*>(ap);
            a[i][1] = *reinterpret_cast<const unsigned*>(ap + 8 * K);
            a[i][2] = *reinterpret_cast<const unsigned*>(ap + 8);
            a[i][3] = *reinterpret_cast<const unsigned*>(ap + 8 * K + 8);
        }
#pragma unroll
        for (int j = 0; j < 5; j++) {
            const uint2 b = *reinterpret_cast<const uint2*>(
                g_W4T + (size_t)(j * 8 + gid) * K + k0 + tig * 4);
#pragma unroll
            for (int i = 0; i < 2; i++) {
                asm volatile(
                    "mma.sync.aligned.m16n8k16.row.col.f32.f16.f16.f32 "
                    "{%0,%1,%2,%3}, {%4,%5,%6,%7}, {%8,%9}, {%0,%1,%2,%3};"
                    : "+f"(c[i][j][0]), "+f"(c[i][j][1]), "+f"(c[i][j][2]), "+f"(c[i][j][3])
                    : "r"(a[i][0]), "r"(a[i][1]), "r"(a[i][2]), "r"(a[i][3]),
                      "r"(b.x), "r"(b.y));
            }
        }
    }

#pragma unroll
    for (int i = 0; i < 2; i++) {
        const int r0 = mbase + i * 16 + gid;
#pragma unroll
        for (int j = 0; j < 5; j++) {
            const int col = j * 8 + 2 * tig;
            if (r0 < NNODES)
                *reinterpret_cast<__half2*>(C + (size_t)r0 * NCLS + col) =
                    __floats2half2_rn(c[i][j][0], c[i][j][1]);
            if (r0 + 8 < NNODES)
                *reinterpret_cast<__half2*>(C + (size_t)(r0 + 8) * NCLS + col) =
                    __floats2half2_rn(c[i][j][2], c[i][j][3]);
        }
    }
}

// ---------------- launch ----------------
extern "C" void kernel_launch(void* const* d_in, const int* in_sizes, int n_in,
                              void* d_out, int out_size) {
    const float* x = (const float*)d_in[0];
    const int* ei = (const int*)d_in[1];
    const float* W1 = (const float*)d_in[2];
    const float* b1 = (const float*)d_in[3];
    const float* W2 = (const float*)d_in[4];
    const float* b2 = (const float*)d_in[5];
    const float* W3 = (const float*)d_in[6];
    const float* b3 = (const float*)d_in[7];
    const float* W4 = (const float*)d_in[8];
    const float* b4 = (const float*)d_in[9];
    float* out = (float*)d_out;
    const int E = in_sizes[1] / 2;

    k_prep<<<(NXCONV + 255) / 256, 256>>>(x, W1, W2, W3, W4, 1);  // xconv -> B, hist=0, WTs
    k_hist<<<(E + 255) / 256, 256>>>(ei, E);
    k_scan_s1<<<NBLK256, 256>>>();
    k_scan_s2<<<1, 512>>>();
    k_scan_s3<<<NBLK256, 256>>>(E);
    k_scatter<<<(E + 255) / 256, 256>>>(ei, E);

    const int AGG_BLOCKS = (NNODES + 7) / 8;
    const dim3 GG(NPAD / 128, 2);
    const int GS = NPAD / 256;

    // conv1
    k_agg_x_h<<<AGG_BLOCKS, 256>>>(1, 0);                     // B -> A
    k_gemm_mma3<128, true><<<GG, 256>>>(0, 1, b1, 1);         // A -> B

    // conv2
    k_gemm_mma3<256, false><<<GG, 256>>>(1, 2, nullptr, 0);   // B -> A
    k_agg_h256<<<AGG_BLOCKS, 256>>>(0, 1, b2);                // A -> B

    // conv3 (reuses W2/b2)
    k_gemm_mma3<256, false><<<GG, 256>>>(1, 2, nullptr, 0);
    k_agg_h256<<<AGG_BLOCKS, 256>>>(0, 1, b2);

    // conv4
    k_gemm_mma3<256, false><<<GG, 256>>>(1, 3, nullptr, 0);
    k_agg_h256<<<AGG_BLOCKS, 256>>>(0, 1, b3);

    // conv5
    k_gemm_small_mma<<<GS, 256>>>(1, 0);                      // B -> A
    k_agg40_lsm<<<AGG_BLOCKS, 256>>>(0, out, b4);
}